// round 7
// baseline (speedup 1.0000x reference)
#include <cuda_runtime.h>
#include <cuda_bf16.h>
#include <math.h>

#define H      300
#define G3     900
#define NB     2048
#define SEGL   48
#define NTOK   (NB * SEGL)
#define NW     1800

__device__ float g_xp[(size_t)2 * SEGL * NB * G3];
__device__ float g_h[2][2][NB * H];

__device__ __forceinline__ float sigmoidf(float v) { return 1.0f / (1.0f + expf(-v)); }

// ---------------- K1: h0 = segment max ----------------
__global__ void setup_kernel(const float* __restrict__ x) {
    int b = blockIdx.x;
    const float* xb = x + (size_t)b * SEGL * H;
    for (int h = threadIdx.x; h < H; h += blockDim.x) {
        float mx = -INFINITY;
        #pragma unroll 4
        for (int l = 0; l < SEGL; l++) mx = fmaxf(mx, xb[(size_t)l * H + h]);
        g_h[0][0][b * H + h] = mx;
        g_h[1][0][b * H + h] = mx;
    }
}

// ---------------- K2: xp = relu(x+bias) @ W_ih^T + b_ih ----------------
// BM=BN=128, BK=60 (5 k-iters), 256 thr, 8x8 microtile.
__global__ __launch_bounds__(256) void xproj_kernel(
        const float* __restrict__ x, const float* __restrict__ bias,
        const float* __restrict__ wf, const float* __restrict__ wb,
        const float* __restrict__ bf, const float* __restrict__ bb) {
    __shared__ float As[60][128];
    __shared__ float Ws[60][128];

    const int m0 = blockIdx.y * 128;
    const int n0 = blockIdx.x * 128;
    const int tid = threadIdx.x;
    const int ty = tid >> 4, tx = tid & 15;

    float acc[8][8] = {};

    for (int k0 = 0; k0 < H; k0 += 60) {
        // A: 128 rows x 15 float4 = 1920 f4
        #pragma unroll
        for (int it = 0; it < 8; it++) {
            int t = tid + it * 256;
            if (t < 1920) {
                int row = t / 15, kq = t % 15;
                int k = k0 + kq * 4;
                float4 v  = *reinterpret_cast<const float4*>(x + (size_t)(m0 + row) * H + k);
                float4 bv = *reinterpret_cast<const float4*>(bias + k);
                As[kq * 4 + 0][row] = fmaxf(v.x + bv.x, 0.0f);
                As[kq * 4 + 1][row] = fmaxf(v.y + bv.y, 0.0f);
                As[kq * 4 + 2][row] = fmaxf(v.z + bv.z, 0.0f);
                As[kq * 4 + 3][row] = fmaxf(v.w + bv.w, 0.0f);
            }
        }
        // W: 128 n-rows x 15 f4
        #pragma unroll
        for (int it = 0; it < 8; it++) {
            int t = tid + it * 256;
            if (t < 1920) {
                int row = t / 15, kq = t % 15;
                int n = n0 + row;
                int k = k0 + kq * 4;
                float4 v = make_float4(0.f, 0.f, 0.f, 0.f);
                if (n < NW) {
                    const float* w = (n < G3) ? wf : wb;
                    int g = (n < G3) ? n : n - G3;
                    v = *reinterpret_cast<const float4*>(w + (size_t)g * H + k);
                }
                Ws[kq * 4 + 0][row] = v.x;
                Ws[kq * 4 + 1][row] = v.y;
                Ws[kq * 4 + 2][row] = v.z;
                Ws[kq * 4 + 3][row] = v.w;
            }
        }
        __syncthreads();

        #pragma unroll
        for (int kk = 0; kk < 60; kk++) {
            float a[8], b[8];
            *reinterpret_cast<float4*>(a)     = *reinterpret_cast<const float4*>(&As[kk][ty * 8]);
            *reinterpret_cast<float4*>(a + 4) = *reinterpret_cast<const float4*>(&As[kk][ty * 8 + 4]);
            *reinterpret_cast<float4*>(b)     = *reinterpret_cast<const float4*>(&Ws[kk][tx * 8]);
            *reinterpret_cast<float4*>(b + 4) = *reinterpret_cast<const float4*>(&Ws[kk][tx * 8 + 4]);
            #pragma unroll
            for (int i = 0; i < 8; i++)
                #pragma unroll
                for (int j = 0; j < 8; j++)
                    acc[i][j] = fmaf(a[i], b[j], acc[i][j]);
        }
        __syncthreads();
    }

    #pragma unroll
    for (int i = 0; i < 8; i++) {
        int m = m0 + ty * 8 + i;
        int b = m / SEGL, l = m % SEGL;
        #pragma unroll
        for (int j = 0; j < 8; j++) {
            int n = n0 + tx * 8 + j;
            if (n >= NW) continue;
            int d = (n >= G3) ? 1 : 0;
            int g = n - d * G3;
            float bv = d ? __ldg(bb + g) : __ldg(bf + g);
            size_t oi = (((size_t)d * SEGL + l) * NB + b) * (size_t)G3 + g;
            g_xp[oi] = acc[i][j] + bv;
        }
    }
}

// ---------------- K3: one GRU step, both directions ----------------
// 64 molecules x 32 hcols x 3 gates per CTA, 128 thr (8x16), 8x2x3 microtile.
// BK=60 (5 k-iters). grid = 10 x 32 x 2 = 640 CTAs -> single wave, ~5 CTAs/SM.
__global__ __launch_bounds__(128) void gru_step_kernel(
        int s,
        const float* __restrict__ whf, const float* __restrict__ whb,
        const float* __restrict__ bhf, const float* __restrict__ bhb,
        float* __restrict__ out) {
    const int d  = blockIdx.z;
    const int l  = d ? (SEGL - 1 - s) : s;
    const int pp = s & 1;
    const float* w     = d ? whb : whf;
    const float* bhh   = d ? bhb : bhf;
    const float* h_in  = g_h[d][pp];
    float*       h_out = g_h[d][pp ^ 1];
    const float* xp    = g_xp + ((size_t)d * SEGL + l) * NB * G3;

    const int m0 = blockIdx.y * 64;
    const int h0 = blockIdx.x * 32;
    const int tid = threadIdx.x;
    const int ty = tid >> 4, tx = tid & 15;   // rows ty*8..+7, hcols tx*2..+1

    __shared__ float As[60][64];       // 15.36 KB
    __shared__ float Bs[3][60][32];    // 23.04 KB

    float ar[8][2] = {}, az[8][2] = {}, an[8][2] = {};

    for (int k0 = 0; k0 < H; k0 += 60) {
        // h_in tile: 64 rows x 15 f4 = 960 f4
        #pragma unroll
        for (int it = 0; it < 8; it++) {
            int t = tid + it * 128;
            if (t < 960) {
                int row = t / 15, kq = t % 15;
                int k = k0 + kq * 4;
                float4 v = *reinterpret_cast<const float4*>(h_in + (size_t)(m0 + row) * H + k);
                As[kq * 4 + 0][row] = v.x;
                As[kq * 4 + 1][row] = v.y;
                As[kq * 4 + 2][row] = v.z;
                As[kq * 4 + 3][row] = v.w;
            }
        }
        // W_hh tile: 3 x 32 x 15 f4 = 1440 f4
        #pragma unroll
        for (int it = 0; it < 12; it++) {
            int t = tid + it * 128;
            if (t < 1440) {
                int g = t / 480, rem = t % 480;
                int hc = rem / 15, kq = rem % 15;
                int hcol = h0 + hc;
                int k = k0 + kq * 4;
                float4 v = make_float4(0.f, 0.f, 0.f, 0.f);
                if (hcol < H)
                    v = *reinterpret_cast<const float4*>(w + ((size_t)g * H + hcol) * H + k);
                Bs[g][kq * 4 + 0][hc] = v.x;
                Bs[g][kq * 4 + 1][hc] = v.y;
                Bs[g][kq * 4 + 2][hc] = v.z;
                Bs[g][kq * 4 + 3][hc] = v.w;
            }
        }
        __syncthreads();

        #pragma unroll
        for (int kk = 0; kk < 60; kk++) {
            float a[8];
            *reinterpret_cast<float4*>(a)     = *reinterpret_cast<const float4*>(&As[kk][ty * 8]);
            *reinterpret_cast<float4*>(a + 4) = *reinterpret_cast<const float4*>(&As[kk][ty * 8 + 4]);
            float br[2], bz[2], bn[2];
            *reinterpret_cast<float2*>(br) = *reinterpret_cast<const float2*>(&Bs[0][kk][tx * 2]);
            *reinterpret_cast<float2*>(bz) = *reinterpret_cast<const float2*>(&Bs[1][kk][tx * 2]);
            *reinterpret_cast<float2*>(bn) = *reinterpret_cast<const float2*>(&Bs[2][kk][tx * 2]);
            #pragma unroll
            for (int i = 0; i < 8; i++) {
                #pragma unroll
                for (int j = 0; j < 2; j++) {
                    ar[i][j] = fmaf(a[i], br[j], ar[i][j]);
                    az[i][j] = fmaf(a[i], bz[j], az[i][j]);
                    an[i][j] = fmaf(a[i], bn[j], an[i][j]);
                }
            }
        }
        __syncthreads();
    }

    #pragma unroll
    for (int i = 0; i < 8; i++) {
        int m = m0 + ty * 8 + i;
        const float* xrow = xp + (size_t)m * G3;
        #pragma unroll
        for (int j = 0; j < 2; j++) {
            int hcol = h0 + tx * 2 + j;
            if (hcol >= H) continue;
            float hr = ar[i][j] + __ldg(bhh + hcol);
            float hz = az[i][j] + __ldg(bhh + H + hcol);
            float hn = an[i][j] + __ldg(bhh + 2 * H + hcol);
            float r  = sigmoidf(xrow[hcol] + hr);
            float z  = sigmoidf(xrow[H + hcol] + hz);
            float nn = tanhf(xrow[2 * H + hcol] + r * hn);
            float hp = h_in[(size_t)m * H + hcol];
            float hnew = (1.0f - z) * nn + z * hp;
            h_out[(size_t)m * H + hcol] = hnew;
            out[((size_t)m * SEGL + l) * (2 * H) + (size_t)d * H + hcol] = hnew;
        }
    }
}

// ---------------- launch ----------------
extern "C" void kernel_launch(void* const* d_in, const int* in_sizes, int n_in,
                              void* d_out, int out_size) {
    const float* x      = (const float*)d_in[0];
    const float* bias   = (const float*)d_in[4];
    const float* w_ih_f = (const float*)d_in[5];
    const float* w_hh_f = (const float*)d_in[6];
    const float* b_ih_f = (const float*)d_in[7];
    const float* b_hh_f = (const float*)d_in[8];
    const float* w_ih_b = (const float*)d_in[9];
    const float* w_hh_b = (const float*)d_in[10];
    const float* b_ih_b = (const float*)d_in[11];
    const float* b_hh_b = (const float*)d_in[12];
    float* out = (float*)d_out;

    setup_kernel<<<NB, 128>>>(x);

    dim3 g2((NW + 127) / 128, NTOK / 128);   // 15 x 768
    xproj_kernel<<<g2, 256>>>(x, bias, w_ih_f, w_ih_b, b_ih_f, b_ih_b);

    dim3 g3((H + 31) / 32, NB / 64, 2);      // 10 x 32 x 2 = 640
    for (int s = 0; s < SEGL; s++) {
        gru_step_kernel<<<g3, 128>>>(s, w_hh_f, w_hh_b, b_hh_f, b_hh_b, out);
    }
}

// round 9
// speedup vs baseline: 2.0568x; 2.0568x over previous
#include <cuda_runtime.h>
#include <cuda_bf16.h>
#include <math.h>
#include <stdint.h>

#define H    300
#define G3   900
#define NB   2048
#define SEGL 48
#define NW   1800
#define KP   320   // K padded: 10 chunks of 32

// ---------------- device scratch (zero-initialized at module load) ----------------
__device__ float g_xpt[(size_t)2 * SEGL * G3 * NB];              // [d][l][n=g*300+hc][m]
__device__ float g_hf[(size_t)2 * 2 * KP * NB];                  // [d][pp][k][m] fp32
__device__ __nv_bfloat16 g_hb[(size_t)2 * 2 * 2 * NB * KP];      // [d][pp][hl][m][KP]
__device__ __nv_bfloat16 g_wpk[(size_t)2 * 4 * 2 * 10 * 240 * 32]; // [d][nt][hl][c][240][32]

__device__ __forceinline__ __nv_bfloat16* HB(int d, int pp, int hl) {
    return g_hb + ((size_t)(((d * 2 + pp) * 2) + hl)) * NB * KP;
}
__device__ __forceinline__ float sigmoidf(float v) { return 1.0f / (1.0f + expf(-v)); }

__device__ __forceinline__ void mma16816(float* c, const uint32_t* a, uint32_t b0, uint32_t b1) {
    asm volatile("mma.sync.aligned.m16n8k16.row.col.f32.bf16.bf16.f32 "
        "{%0,%1,%2,%3}, {%4,%5,%6,%7}, {%8,%9}, {%0,%1,%2,%3};"
        : "+f"(c[0]), "+f"(c[1]), "+f"(c[2]), "+f"(c[3])
        : "r"(a[0]), "r"(a[1]), "r"(a[2]), "r"(a[3]), "r"(b0), "r"(b1));
}

// ---------------- setup: h0 = segment max -> hf (transposed) + hb hi/lo ----------------
__global__ void setup_h0(const float* __restrict__ x) {
    int b = blockIdx.x;
    const float* xb = x + (size_t)b * SEGL * H;
    for (int h = threadIdx.x; h < H; h += blockDim.x) {
        float mx = -INFINITY;
        #pragma unroll 4
        for (int l = 0; l < SEGL; l++) mx = fmaxf(mx, xb[(size_t)l * H + h]);
        __nv_bfloat16 hi = __float2bfloat16(mx);
        __nv_bfloat16 lo = __float2bfloat16(mx - __bfloat162float(hi));
        for (int d = 0; d < 2; d++) {
            g_hf[((size_t)(d * 2 + 0) * KP + h) * NB + b] = mx;
            HB(d, 0, 0)[(size_t)b * KP + h] = hi;
            HB(d, 0, 1)[(size_t)b * KP + h] = lo;
        }
    }
}

// ---------------- prep: W_hh -> gate-blocked hi/lo k32 slabs ----------------
// slab (d,nt,hl,c): rows r = g*80 + hcl (hc = nt*80+hcl), 32 k-cols, contiguous.
__global__ void prep_whh(const float* __restrict__ whf, const float* __restrict__ whb) {
    int c = blockIdx.x, nt = blockIdx.y, d = blockIdx.z;
    const float* w = d ? whb : whf;
    __nv_bfloat16* hi_base = g_wpk + (size_t)(((d * 4 + nt) * 2 + 0) * 10 + c) * 7680;
    __nv_bfloat16* lo_base = g_wpk + (size_t)(((d * 4 + nt) * 2 + 1) * 10 + c) * 7680;
    for (int e = threadIdx.x; e < 7680; e += blockDim.x) {
        int row = e >> 5, col = e & 31;
        int g = row / 80, hcl = row % 80;
        int hc = nt * 80 + hcl;
        int k = c * 32 + col;
        float v = (hc < H && k < H) ? w[(size_t)(g * H + hc) * H + k] : 0.0f;
        __nv_bfloat16 hi = __float2bfloat16(v);
        __nv_bfloat16 lo = __float2bfloat16(v - __bfloat162float(hi));
        hi_base[e] = hi;
        lo_base[e] = lo;
    }
}

// ---------------- xproj: xpt[d][l][n][m] = relu(x+bias) @ W_ih^T + b_ih ----------------
union SmemX {
    struct { float As[20][128]; float Ws[20][128]; } t;
    float stage[32][132];
};
__global__ __launch_bounds__(256) void xproj_kernel(
        const float* __restrict__ x, const float* __restrict__ bias,
        const float* __restrict__ wf, const float* __restrict__ wb,
        const float* __restrict__ bf, const float* __restrict__ bb) {
    __shared__ SmemX sm;
    const int n0 = blockIdx.x * 128;
    const int l  = blockIdx.y >> 4;
    const int b0 = (blockIdx.y & 15) * 128;
    const int tid = threadIdx.x;
    const int ty = tid >> 4, tx = tid & 15;

    float acc[8][8] = {};

    for (int k0 = 0; k0 < H; k0 += 20) {
        for (int t = tid; t < 640; t += 256) {
            int row = t / 5, kq = t % 5;
            int k = k0 + kq * 4;
            size_t tok = (size_t)(b0 + row) * SEGL + l;
            float4 v  = *reinterpret_cast<const float4*>(x + tok * H + k);
            float4 bv = *reinterpret_cast<const float4*>(bias + k);
            sm.t.As[kq * 4 + 0][row] = fmaxf(v.x + bv.x, 0.0f);
            sm.t.As[kq * 4 + 1][row] = fmaxf(v.y + bv.y, 0.0f);
            sm.t.As[kq * 4 + 2][row] = fmaxf(v.z + bv.z, 0.0f);
            sm.t.As[kq * 4 + 3][row] = fmaxf(v.w + bv.w, 0.0f);
        }
        for (int t = tid; t < 640; t += 256) {
            int row = t / 5, kq = t % 5;
            int n = n0 + row;
            int k = k0 + kq * 4;
            float4 v = make_float4(0.f, 0.f, 0.f, 0.f);
            if (n < NW) {
                const float* w = (n < G3) ? wf : wb;
                int g = (n < G3) ? n : n - G3;
                v = *reinterpret_cast<const float4*>(w + (size_t)g * H + k);
            }
            sm.t.Ws[kq * 4 + 0][row] = v.x;
            sm.t.Ws[kq * 4 + 1][row] = v.y;
            sm.t.Ws[kq * 4 + 2][row] = v.z;
            sm.t.Ws[kq * 4 + 3][row] = v.w;
        }
        __syncthreads();
        #pragma unroll
        for (int kk = 0; kk < 20; kk++) {
            float a[8], b[8];
            *reinterpret_cast<float4*>(a)     = *reinterpret_cast<const float4*>(&sm.t.As[kk][ty * 8]);
            *reinterpret_cast<float4*>(a + 4) = *reinterpret_cast<const float4*>(&sm.t.As[kk][ty * 8 + 4]);
            *reinterpret_cast<float4*>(b)     = *reinterpret_cast<const float4*>(&sm.t.Ws[kk][tx * 8]);
            *reinterpret_cast<float4*>(b + 4) = *reinterpret_cast<const float4*>(&sm.t.Ws[kk][tx * 8 + 4]);
            #pragma unroll
            for (int i = 0; i < 8; i++)
                #pragma unroll
                for (int j = 0; j < 8; j++)
                    acc[i][j] = fmaf(a[i], b[j], acc[i][j]);
        }
        __syncthreads();
    }

    for (int gi = 0; gi < 4; gi++) {
        if ((tx >> 2) == gi) {
            #pragma unroll
            for (int j = 0; j < 8; j++) {
                int n = n0 + tx * 8 + j;
                float bv = (n < G3) ? __ldg(bf + n) : ((n < NW) ? __ldg(bb + n - G3) : 0.0f);
                #pragma unroll
                for (int i = 0; i < 8; i++)
                    sm.stage[(tx & 3) * 8 + j][ty * 8 + i] = acc[i][j] + bv;
            }
        }
        __syncthreads();
        for (int e = tid; e < 4096; e += 256) {
            int nl = e >> 7, ml = e & 127;
            int n = n0 + gi * 32 + nl;
            if (n < NW) {
                int d = (n >= G3) ? 1 : 0;
                int q = n - d * G3;
                g_xpt[((size_t)(d * SEGL + l) * G3 + q) * NB + b0 + ml] = sm.stage[nl][ml];
            }
        }
        __syncthreads();
    }
}

// ---------------- gru step: mma.sync bf16 split + fused epilogue ----------------
// grid (4 nt, 32 mt, 2 d) = 256 CTAs, 256 thr (8 warps: 4 wm x 2 wn).
// CTA: 64 molecules x 240 gate-rows, K=320 in 10 k32 chunks.
#define A_STRIDE 40
#define B_STRIDE 40
__global__ __launch_bounds__(256) void gru_step_mma(
        int s, const float* __restrict__ bhf, const float* __restrict__ bhb,
        float* __restrict__ out) {
    extern __shared__ char smraw[];
    __nv_bfloat16* As = (__nv_bfloat16*)smraw;                       // [2][64][A_STRIDE]
    __nv_bfloat16* Bs = (__nv_bfloat16*)(smraw + 2 * 64 * A_STRIDE * 2); // [2][240][B_STRIDE]
    float* Gs = (float*)smraw;                                       // [64][241] (reuse)

    const int nt = blockIdx.x, mt = blockIdx.y, d = blockIdx.z;
    const int l  = d ? (SEGL - 1 - s) : s;
    const int pp = s & 1;
    const int tid = threadIdx.x;
    const int wid = tid >> 5, lane = tid & 31;
    const int wm = wid >> 1, wn = wid & 1;
    const int grp = lane >> 2, tig = lane & 3;
    const int m0 = mt * 64;

    const char* h_hi = (const char*)HB(d, pp, 0) + (size_t)m0 * KP * 2;
    const char* h_lo = (const char*)HB(d, pp, 1) + (size_t)m0 * KP * 2;
    const __nv_bfloat16* wslab = g_wpk + (size_t)((d * 4 + nt) * 2) * 10 * 7680;

    float acc[15][4] = {};

    for (int c = 0; c < 10; c++) {
        const int k0 = c * 32;
        // A: 2 hl x 64 rows x 4 uint4
        for (int t = tid; t < 512; t += 256) {
            int row = t >> 3, hl = (t >> 2) & 1, q = t & 3;
            const char* src = (hl ? h_lo : h_hi) + ((size_t)row * KP + k0) * 2 + q * 16;
            *(uint4*)((char*)As + ((hl * 64 + row) * A_STRIDE) * 2 + q * 16) = *(const uint4*)src;
        }
        // B: 2 hl x 240 rows x 4 uint4 (source slab contiguous [240][32])
        for (int t = tid; t < 1920; t += 256) {
            int hl = t / 960, idx = t - hl * 960;
            int row = idx >> 2, q = idx & 3;
            const char* src = (const char*)(wslab + (size_t)(hl * 10 + c) * 7680) + row * 64 + q * 16;
            *(uint4*)((char*)Bs + ((hl * 240 + row) * B_STRIDE) * 2 + q * 16) = *(const uint4*)src;
        }
        __syncthreads();

        uint32_t ah[2][4], al[2][4];
        #pragma unroll
        for (int kk = 0; kk < 2; kk++) {
            int r = wm * 16 + grp;
            int k = kk * 16 + tig * 2;
            ah[kk][0] = *(const uint32_t*)&As[(0 * 64 + r) * A_STRIDE + k];
            ah[kk][1] = *(const uint32_t*)&As[(0 * 64 + r + 8) * A_STRIDE + k];
            ah[kk][2] = *(const uint32_t*)&As[(0 * 64 + r) * A_STRIDE + k + 8];
            ah[kk][3] = *(const uint32_t*)&As[(0 * 64 + r + 8) * A_STRIDE + k + 8];
            al[kk][0] = *(const uint32_t*)&As[(1 * 64 + r) * A_STRIDE + k];
            al[kk][1] = *(const uint32_t*)&As[(1 * 64 + r + 8) * A_STRIDE + k];
            al[kk][2] = *(const uint32_t*)&As[(1 * 64 + r) * A_STRIDE + k + 8];
            al[kk][3] = *(const uint32_t*)&As[(1 * 64 + r + 8) * A_STRIDE + k + 8];
        }
        #pragma unroll
        for (int t8 = 0; t8 < 15; t8++) {
            int br = wn * 120 + t8 * 8 + grp;
            #pragma unroll
            for (int kk = 0; kk < 2; kk++) {
                int k = kk * 16 + tig * 2;
                uint32_t bh0 = *(const uint32_t*)&Bs[(0 * 240 + br) * B_STRIDE + k];
                uint32_t bh1 = *(const uint32_t*)&Bs[(0 * 240 + br) * B_STRIDE + k + 8];
                uint32_t bl0 = *(const uint32_t*)&Bs[(1 * 240 + br) * B_STRIDE + k];
                uint32_t bl1 = *(const uint32_t*)&Bs[(1 * 240 + br) * B_STRIDE + k + 8];
                mma16816(acc[t8], ah[kk], bh0, bh1);
                mma16816(acc[t8], ah[kk], bl0, bl1);
                mma16816(acc[t8], al[kk], bh0, bh1);
            }
        }
        __syncthreads();
    }

    // ---- stage G into SMEM (reuses A/B space) ----
    #pragma unroll
    for (int t8 = 0; t8 < 15; t8++) {
        int row = wm * 16 + grp;
        int col = wn * 120 + t8 * 8 + tig * 2;
        Gs[row * 241 + col]           = acc[t8][0];
        Gs[row * 241 + col + 1]       = acc[t8][1];
        Gs[(row + 8) * 241 + col]     = acc[t8][2];
        Gs[(row + 8) * 241 + col + 1] = acc[t8][3];
    }
    __syncthreads();

    // ---- fused gate epilogue ----
    const float* xd   = g_xpt + (size_t)(d * SEGL + l) * G3 * NB;
    const float* bh   = d ? bhb : bhf;
    const float* hfin = g_hf + (size_t)(d * 2 + pp) * KP * NB;
    float*      hfout = g_hf + (size_t)(d * 2 + (pp ^ 1)) * KP * NB;
    const int nvalid = (nt == 3) ? 60 : 80;

    for (int e = tid; e < 64 * 80; e += 256) {
        int ml = e & 63, hcl = e >> 6;
        if (hcl < nvalid) {
            int m = m0 + ml;
            int hc = nt * 80 + hcl;
            float hr = Gs[ml * 241 + hcl]        + __ldg(bh + hc);
            float hz = Gs[ml * 241 + 80 + hcl]   + __ldg(bh + H + hc);
            float hn = Gs[ml * 241 + 160 + hcl]  + __ldg(bh + 2 * H + hc);
            float xr = xd[(size_t)hc * NB + m];
            float xz = xd[(size_t)(H + hc) * NB + m];
            float xn = xd[(size_t)(2 * H + hc) * NB + m];
            float r  = sigmoidf(xr + hr);
            float z  = sigmoidf(xz + hz);
            float nv = tanhf(xn + r * hn);
            float hp = hfin[(size_t)hc * NB + m];
            float hnew = (1.0f - z) * nv + z * hp;
            hfout[(size_t)hc * NB + m] = hnew;
            __nv_bfloat16 hi = __float2bfloat16(hnew);
            __nv_bfloat16 lo = __float2bfloat16(hnew - __bfloat162float(hi));
            uint32_t packed = (uint32_t)*(uint16_t*)&hi | ((uint32_t)*(uint16_t*)&lo << 16);
            Gs[ml * 241 + hcl] = hnew;                      // overwrite r-slot: fp32 h
            Gs[ml * 241 + 80 + hcl] = __uint_as_float(packed); // overwrite z-slot: packed bf16
        }
    }
    __syncthreads();

    // coalesced out write (staged)
    {
        const int nq = (nt == 3) ? 15 : 20;
        for (int e = tid; e < 64 * nq; e += 256) {
            int ml = e / nq, q = e - ml * nq;
            int m = m0 + ml;
            float4 v = make_float4(Gs[ml * 241 + q * 4],     Gs[ml * 241 + q * 4 + 1],
                                   Gs[ml * 241 + q * 4 + 2], Gs[ml * 241 + q * 4 + 3]);
            *(float4*)(out + ((size_t)m * SEGL + l) * (2 * H) + (size_t)d * H + nt * 80 + q * 4) = v;
        }
    }
    // coalesced packed bf16 h write (staged)
    {
        __nv_bfloat16* ho_hi = HB(d, pp ^ 1, 0);
        __nv_bfloat16* ho_lo = HB(d, pp ^ 1, 1);
        const int nj = (nt == 3) ? 30 : 40;   // u32 pairs (2 hcols each)
        for (int e = tid; e < 64 * nj; e += 256) {
            int ml = e / nj, j = e - ml * nj;
            int m = m0 + ml;
            uint32_t p0 = __float_as_uint(Gs[ml * 241 + 80 + 2 * j]);
            uint32_t p1 = __float_as_uint(Gs[ml * 241 + 80 + 2 * j + 1]);
            uint32_t hiw = (p0 & 0xFFFFu) | (p1 << 16);
            uint32_t low = (p0 >> 16) | (p1 & 0xFFFF0000u);
            size_t off = ((size_t)m * KP + nt * 80 + 2 * j);
            *(uint32_t*)((char*)ho_hi + off * 2) = hiw;
            *(uint32_t*)((char*)ho_lo + off * 2) = low;
        }
    }
}

// ---------------- launch ----------------
extern "C" void kernel_launch(void* const* d_in, const int* in_sizes, int n_in,
                              void* d_out, int out_size) {
    const float* x      = (const float*)d_in[0];
    const float* bias   = (const float*)d_in[4];
    const float* w_ih_f = (const float*)d_in[5];
    const float* w_hh_f = (const float*)d_in[6];
    const float* b_ih_f = (const float*)d_in[7];
    const float* b_hh_f = (const float*)d_in[8];
    const float* w_ih_b = (const float*)d_in[9];
    const float* w_hh_b = (const float*)d_in[10];
    const float* b_ih_b = (const float*)d_in[11];
    const float* b_hh_b = (const float*)d_in[12];
    float* out = (float*)d_out;

    // dyn smem: max(mma bufs = (2*64*40 + 2*240*40)*2 = 48640, Gs = 64*241*4 = 61696)
    static int attr_set = 0;
    if (!attr_set) {
        cudaFuncSetAttribute(gru_step_mma, cudaFuncAttributeMaxDynamicSharedMemorySize, 61696);
        attr_set = 1;
    }

    setup_h0<<<NB, 128>>>(x);
    prep_whh<<<dim3(10, 4, 2), 256>>>(w_hh_f, w_hh_b);

    dim3 g2(15, SEGL * 16);
    xproj_kernel<<<g2, 256>>>(x, bias, w_ih_f, w_ih_b, b_ih_f, b_ih_b);

    dim3 g3(4, 32, 2);
    for (int s = 0; s < SEGL; s++) {
        gru_step_mma<<<g3, 256, 61696>>>(s, b_hh_f, b_hh_b, out);
    }
}

// round 10
// speedup vs baseline: 2.9748x; 1.4463x over previous
#include <cuda_runtime.h>
#include <cuda_bf16.h>
#include <math.h>
#include <stdint.h>

#define H    300
#define G3   900
#define NB   2048
#define SEGL 48
#define NW   1800
#define KP   320   // K padded: 10 chunks of 32

#define A_STRIDE 40
#define B_STRIDE 40
// smem layout (both MMA kernels): As [2buf][2hl][64][40] bf16 = 20480B,
// Bs at +20480: [2buf][2hl][240][40] bf16 = 76800B, total 97280B. Gs overlays start.
#define SMEM_BYTES 97280

// ---------------- device scratch (zero-initialized at module load) ----------------
__device__ float g_xpt[(size_t)2 * SEGL * G3 * NB];                // [d][l][n=g*300+hc][m]
__device__ float g_hf[(size_t)2 * 2 * KP * NB];                    // [d][pp][k][m] fp32
__device__ __nv_bfloat16 g_hb[(size_t)2 * 2 * 2 * NB * KP];        // [d][pp][hl][m][KP]
__device__ __nv_bfloat16 g_wpk[(size_t)2 * 4 * 2 * 10 * 7680];     // W_hh slabs
__device__ __nv_bfloat16 g_wih_pk[(size_t)8 * 2 * 10 * 7680];      // W_ih slabs (N padded 1920)

__device__ __forceinline__ __nv_bfloat16* HB(int d, int pp, int hl) {
    return g_hb + ((size_t)(((d * 2 + pp) * 2) + hl)) * NB * KP;
}
__device__ __forceinline__ float sigmoidf(float v) { return 1.0f / (1.0f + expf(-v)); }

__device__ __forceinline__ void mma16816(float* c, const uint32_t* a, uint32_t b0, uint32_t b1) {
    asm volatile("mma.sync.aligned.m16n8k16.row.col.f32.bf16.bf16.f32 "
        "{%0,%1,%2,%3}, {%4,%5,%6,%7}, {%8,%9}, {%0,%1,%2,%3};"
        : "+f"(c[0]), "+f"(c[1]), "+f"(c[2]), "+f"(c[3])
        : "r"(a[0]), "r"(a[1]), "r"(a[2]), "r"(a[3]), "r"(b0), "r"(b1));
}
__device__ __forceinline__ void cpa16(uint32_t dst, const void* src) {
    asm volatile("cp.async.cg.shared.global [%0], [%1], 16;" :: "r"(dst), "l"(src));
}
#define CP_COMMIT() asm volatile("cp.async.commit_group;")
#define CP_WAIT1()  asm volatile("cp.async.wait_group 1;")
#define CP_WAIT0()  asm volatile("cp.async.wait_group 0;")

// ---------------- setup: h0 = segment max -> hf (transposed) + hb hi/lo ----------------
__global__ void setup_h0(const float* __restrict__ x) {
    int b = blockIdx.x;
    const float* xb = x + (size_t)b * SEGL * H;
    for (int h = threadIdx.x; h < H; h += blockDim.x) {
        float mx = -INFINITY;
        #pragma unroll 4
        for (int l = 0; l < SEGL; l++) mx = fmaxf(mx, xb[(size_t)l * H + h]);
        __nv_bfloat16 hi = __float2bfloat16(mx);
        __nv_bfloat16 lo = __float2bfloat16(mx - __bfloat162float(hi));
        for (int d = 0; d < 2; d++) {
            g_hf[((size_t)(d * 2 + 0) * KP + h) * NB + b] = mx;
            HB(d, 0, 0)[(size_t)b * KP + h] = hi;
            HB(d, 0, 1)[(size_t)b * KP + h] = lo;
        }
    }
}

// ---------------- prep: W_hh -> gate-blocked hi/lo k32 slabs ----------------
__global__ void prep_whh(const float* __restrict__ whf, const float* __restrict__ whb) {
    int c = blockIdx.x, nt = blockIdx.y, d = blockIdx.z;
    const float* w = d ? whb : whf;
    __nv_bfloat16* hi_base = g_wpk + (size_t)(((d * 4 + nt) * 2 + 0) * 10 + c) * 7680;
    __nv_bfloat16* lo_base = g_wpk + (size_t)(((d * 4 + nt) * 2 + 1) * 10 + c) * 7680;
    for (int e = threadIdx.x; e < 7680; e += blockDim.x) {
        int row = e >> 5, col = e & 31;
        int g = row / 80, hcl = row % 80;
        int hc = nt * 80 + hcl;
        int k = c * 32 + col;
        float v = (hc < H && k < H) ? w[(size_t)(g * H + hc) * H + k] : 0.0f;
        __nv_bfloat16 hi = __float2bfloat16(v);
        __nv_bfloat16 lo = __float2bfloat16(v - __bfloat162float(hi));
        hi_base[e] = hi;
        lo_base[e] = lo;
    }
}

// ---------------- prep: W_ih -> hi/lo k32 slabs, N padded to 1920 ----------------
// n = nt*240 + row; n<900 -> w_ih_f[n], n<1800 -> w_ih_b[n-900], else 0.
__global__ void prep_wih(const float* __restrict__ wif, const float* __restrict__ wib) {
    int c = blockIdx.x, nt = blockIdx.y;
    __nv_bfloat16* hi_base = g_wih_pk + (size_t)((nt * 2 + 0) * 10 + c) * 7680;
    __nv_bfloat16* lo_base = g_wih_pk + (size_t)((nt * 2 + 1) * 10 + c) * 7680;
    for (int e = threadIdx.x; e < 7680; e += blockDim.x) {
        int row = e >> 5, col = e & 31;
        int n = nt * 240 + row;
        int k = c * 32 + col;
        float v = 0.0f;
        if (k < H) {
            if (n < G3)      v = wif[(size_t)n * H + k];
            else if (n < NW) v = wib[(size_t)(n - G3) * H + k];
        }
        __nv_bfloat16 hi = __float2bfloat16(v);
        __nv_bfloat16 lo = __float2bfloat16(v - __bfloat162float(hi));
        hi_base[e] = hi;
        lo_base[e] = lo;
    }
}

// ---------------- xproj MMA: xpt[d][l][n][m] = relu(x+bias) @ W_ih^T + b_ih ----------------
// grid (8 nt, 32 mt, 48 l), 256 thr. CTA: 64 tokens (fixed l) x 240 n, K=10 k32 chunks.
__global__ __launch_bounds__(256) void xproj_mma(
        const float* __restrict__ x, const float* __restrict__ bias,
        const float* __restrict__ bif, const float* __restrict__ bib) {
    extern __shared__ char smraw[];
    __nv_bfloat16* As = (__nv_bfloat16*)smraw;
    __nv_bfloat16* Bs = (__nv_bfloat16*)(smraw + 20480);
    float* Gs = (float*)smraw;
    uint32_t sBu = (uint32_t)__cvta_generic_to_shared(Bs);

    const int nt = blockIdx.x, mt = blockIdx.y, l = blockIdx.z;
    const int b0 = mt * 64;
    const int tid = threadIdx.x;
    const int wid = tid >> 5, lane = tid & 31;
    const int wm = wid >> 1, wn = wid & 1;
    const int grp = lane >> 2, tig = lane & 3;

    const __nv_bfloat16* wslab = g_wih_pk + (size_t)(nt * 2) * 10 * 7680;

    // per-thread A element ownership: row = tid>>2 (0..63), 8-float group = tid&3
    const int arow = tid >> 2, agrp = tid & 3;
    const size_t xbase = ((size_t)(b0 + arow) * SEGL + l) * H;
    float4 xv0, xv1;

    auto loadX = [&](int c) {
        int k = c * 32 + agrp * 8;
        xv0 = make_float4(0.f, 0.f, 0.f, 0.f);
        xv1 = make_float4(0.f, 0.f, 0.f, 0.f);
        if (k < H) {
            float4 v = *(const float4*)(x + xbase + k);
            float4 bv = *(const float4*)(bias + k);
            xv0 = make_float4(fmaxf(v.x + bv.x, 0.f), fmaxf(v.y + bv.y, 0.f),
                              fmaxf(v.z + bv.z, 0.f), fmaxf(v.w + bv.w, 0.f));
        }
        if (k + 4 < H) {
            float4 v = *(const float4*)(x + xbase + k + 4);
            float4 bv = *(const float4*)(bias + k + 4);
            xv1 = make_float4(fmaxf(v.x + bv.x, 0.f), fmaxf(v.y + bv.y, 0.f),
                              fmaxf(v.z + bv.z, 0.f), fmaxf(v.w + bv.w, 0.f));
        }
    };
    auto writeA = [&](int buf) {
        float vv[8] = {xv0.x, xv0.y, xv0.z, xv0.w, xv1.x, xv1.y, xv1.z, xv1.w};
        union { __nv_bfloat16 h[8]; uint4 u; } ph, pl;
        #pragma unroll
        for (int i = 0; i < 8; i++) {
            __nv_bfloat16 hi = __float2bfloat16(vv[i]);
            ph.h[i] = hi;
            pl.h[i] = __float2bfloat16(vv[i] - __bfloat162float(hi));
        }
        *(uint4*)&As[((buf * 2 + 0) * 64 + arow) * A_STRIDE + agrp * 8] = ph.u;
        *(uint4*)&As[((buf * 2 + 1) * 64 + arow) * A_STRIDE + agrp * 8] = pl.u;
    };
    auto prefetchB = [&](int c, int buf) {
        #pragma unroll
        for (int u = 0; u < 8; u++) {
            int t = tid + u * 256;
            if (t < 1920) {
                int hl = t / 960, idx = t - hl * 960;
                int row = idx >> 2, q = idx & 3;
                const char* src = (const char*)(wslab + (size_t)(hl * 10 + c) * 7680) + row * 64 + q * 16;
                uint32_t dst = sBu + (((buf * 2 + hl) * 240 + row) * B_STRIDE) * 2 + q * 16;
                cpa16(dst, src);
            }
        }
        CP_COMMIT();
    };

    float acc[15][4] = {};

    loadX(0);
    prefetchB(0, 0);
    writeA(0);

    for (int c = 0; c < 10; c++) {
        if (c < 9) { loadX(c + 1); prefetchB(c + 1, (c + 1) & 1); }
        if (c < 9) { CP_WAIT1(); } else { CP_WAIT0(); }
        __syncthreads();
        if (c < 9) writeA((c + 1) & 1);

        const __nv_bfloat16* Ab = As + (c & 1) * 2 * 64 * A_STRIDE;
        const __nv_bfloat16* Bb = Bs + (c & 1) * 2 * 240 * B_STRIDE;

        uint32_t ah[2][4], al[2][4];
        #pragma unroll
        for (int kk = 0; kk < 2; kk++) {
            int r = wm * 16 + grp;
            int k = kk * 16 + tig * 2;
            ah[kk][0] = *(const uint32_t*)&Ab[(0 * 64 + r) * A_STRIDE + k];
            ah[kk][1] = *(const uint32_t*)&Ab[(0 * 64 + r + 8) * A_STRIDE + k];
            ah[kk][2] = *(const uint32_t*)&Ab[(0 * 64 + r) * A_STRIDE + k + 8];
            ah[kk][3] = *(const uint32_t*)&Ab[(0 * 64 + r + 8) * A_STRIDE + k + 8];
            al[kk][0] = *(const uint32_t*)&Ab[(1 * 64 + r) * A_STRIDE + k];
            al[kk][1] = *(const uint32_t*)&Ab[(1 * 64 + r + 8) * A_STRIDE + k];
            al[kk][2] = *(const uint32_t*)&Ab[(1 * 64 + r) * A_STRIDE + k + 8];
            al[kk][3] = *(const uint32_t*)&Ab[(1 * 64 + r + 8) * A_STRIDE + k + 8];
        }
        #pragma unroll
        for (int t8 = 0; t8 < 15; t8++) {
            int br = wn * 120 + t8 * 8 + grp;
            #pragma unroll
            for (int kk = 0; kk < 2; kk++) {
                int k = kk * 16 + tig * 2;
                uint32_t bh0 = *(const uint32_t*)&Bb[(0 * 240 + br) * B_STRIDE + k];
                uint32_t bh1 = *(const uint32_t*)&Bb[(0 * 240 + br) * B_STRIDE + k + 8];
                uint32_t bl0 = *(const uint32_t*)&Bb[(1 * 240 + br) * B_STRIDE + k];
                uint32_t bl1 = *(const uint32_t*)&Bb[(1 * 240 + br) * B_STRIDE + k + 8];
                mma16816(acc[t8], ah[kk], bh0, bh1);
                mma16816(acc[t8], ah[kk], bl0, bl1);
                mma16816(acc[t8], al[kk], bh0, bh1);
            }
        }
        __syncthreads();
    }

    // stage + transposed coalesced write with bias
    #pragma unroll
    for (int t8 = 0; t8 < 15; t8++) {
        int row = wm * 16 + grp;
        int col = wn * 120 + t8 * 8 + tig * 2;
        Gs[row * 241 + col]           = acc[t8][0];
        Gs[row * 241 + col + 1]       = acc[t8][1];
        Gs[(row + 8) * 241 + col]     = acc[t8][2];
        Gs[(row + 8) * 241 + col + 1] = acc[t8][3];
    }
    __syncthreads();

    for (int e = tid; e < 64 * 240; e += 256) {
        int nl = e >> 6, ml = e & 63;
        int n = nt * 240 + nl;
        if (n < NW) {
            int dd = (n >= G3) ? 1 : 0;
            int q = n - dd * G3;
            float bv = dd ? __ldg(bib + q) : __ldg(bif + n);
            g_xpt[((size_t)(dd * SEGL + l) * G3 + q) * NB + b0 + ml] = Gs[ml * 241 + nl] + bv;
        }
    }
}

// ---------------- gru step: double-buffered cp.async + split-bf16 MMA ----------------
// grid (4 nt, 32 mt, 2 d), 256 thr. CTA: 64 molecules x 240 gate-rows, K=10 k32 chunks.
__global__ __launch_bounds__(256) void gru_step_mma(
        int s, const float* __restrict__ bhf, const float* __restrict__ bhb,
        float* __restrict__ out) {
    extern __shared__ char smraw[];
    __nv_bfloat16* As = (__nv_bfloat16*)smraw;
    __nv_bfloat16* Bs = (__nv_bfloat16*)(smraw + 20480);
    float* Gs = (float*)smraw;
    uint32_t sAu = (uint32_t)__cvta_generic_to_shared(As);
    uint32_t sBu = (uint32_t)__cvta_generic_to_shared(Bs);

    const int nt = blockIdx.x, mt = blockIdx.y, d = blockIdx.z;
    const int l  = d ? (SEGL - 1 - s) : s;
    const int pp = s & 1;
    const int tid = threadIdx.x;
    const int wid = tid >> 5, lane = tid & 31;
    const int wm = wid >> 1, wn = wid & 1;
    const int grp = lane >> 2, tig = lane & 3;
    const int m0 = mt * 64;

    const char* h_hi = (const char*)HB(d, pp, 0) + (size_t)m0 * KP * 2;
    const char* h_lo = (const char*)HB(d, pp, 1) + (size_t)m0 * KP * 2;
    const __nv_bfloat16* wslab = g_wpk + (size_t)((d * 4 + nt) * 2) * 10 * 7680;

    auto prefetch = [&](int c, int buf) {
        int k0 = c * 32;
        #pragma unroll
        for (int u = 0; u < 2; u++) {
            int t = tid + u * 256;
            int row = t >> 3, hl = (t >> 2) & 1, q = t & 3;
            const char* src = (hl ? h_lo : h_hi) + ((size_t)row * KP + k0) * 2 + q * 16;
            uint32_t dst = sAu + (((buf * 2 + hl) * 64 + row) * A_STRIDE) * 2 + q * 16;
            cpa16(dst, src);
        }
        #pragma unroll
        for (int u = 0; u < 8; u++) {
            int t = tid + u * 256;
            if (t < 1920) {
                int hl = t / 960, idx = t - hl * 960;
                int row = idx >> 2, q = idx & 3;
                const char* src = (const char*)(wslab + (size_t)(hl * 10 + c) * 7680) + row * 64 + q * 16;
                uint32_t dst = sBu + (((buf * 2 + hl) * 240 + row) * B_STRIDE) * 2 + q * 16;
                cpa16(dst, src);
            }
        }
        CP_COMMIT();
    };

    float acc[15][4] = {};

    prefetch(0, 0);
    for (int c = 0; c < 10; c++) {
        if (c < 9) prefetch(c + 1, (c + 1) & 1);
        if (c < 9) { CP_WAIT1(); } else { CP_WAIT0(); }
        __syncthreads();

        const __nv_bfloat16* Ab = As + (c & 1) * 2 * 64 * A_STRIDE;
        const __nv_bfloat16* Bb = Bs + (c & 1) * 2 * 240 * B_STRIDE;

        uint32_t ah[2][4], al[2][4];
        #pragma unroll
        for (int kk = 0; kk < 2; kk++) {
            int r = wm * 16 + grp;
            int k = kk * 16 + tig * 2;
            ah[kk][0] = *(const uint32_t*)&Ab[(0 * 64 + r) * A_STRIDE + k];
            ah[kk][1] = *(const uint32_t*)&Ab[(0 * 64 + r + 8) * A_STRIDE + k];
            ah[kk][2] = *(const uint32_t*)&Ab[(0 * 64 + r) * A_STRIDE + k + 8];
            ah[kk][3] = *(const uint32_t*)&Ab[(0 * 64 + r + 8) * A_STRIDE + k + 8];
            al[kk][0] = *(const uint32_t*)&Ab[(1 * 64 + r) * A_STRIDE + k];
            al[kk][1] = *(const uint32_t*)&Ab[(1 * 64 + r + 8) * A_STRIDE + k];
            al[kk][2] = *(const uint32_t*)&Ab[(1 * 64 + r) * A_STRIDE + k + 8];
            al[kk][3] = *(const uint32_t*)&Ab[(1 * 64 + r + 8) * A_STRIDE + k + 8];
        }
        #pragma unroll
        for (int t8 = 0; t8 < 15; t8++) {
            int br = wn * 120 + t8 * 8 + grp;
            #pragma unroll
            for (int kk = 0; kk < 2; kk++) {
                int k = kk * 16 + tig * 2;
                uint32_t bh0 = *(const uint32_t*)&Bb[(0 * 240 + br) * B_STRIDE + k];
                uint32_t bh1 = *(const uint32_t*)&Bb[(0 * 240 + br) * B_STRIDE + k + 8];
                uint32_t bl0 = *(const uint32_t*)&Bb[(1 * 240 + br) * B_STRIDE + k];
                uint32_t bl1 = *(const uint32_t*)&Bb[(1 * 240 + br) * B_STRIDE + k + 8];
                mma16816(acc[t8], ah[kk], bh0, bh1);
                mma16816(acc[t8], ah[kk], bl0, bl1);
                mma16816(acc[t8], al[kk], bh0, bh1);
            }
        }
        __syncthreads();
    }

    // ---- stage G ----
    #pragma unroll
    for (int t8 = 0; t8 < 15; t8++) {
        int row = wm * 16 + grp;
        int col = wn * 120 + t8 * 8 + tig * 2;
        Gs[row * 241 + col]           = acc[t8][0];
        Gs[row * 241 + col + 1]       = acc[t8][1];
        Gs[(row + 8) * 241 + col]     = acc[t8][2];
        Gs[(row + 8) * 241 + col + 1] = acc[t8][3];
    }
    __syncthreads();

    // ---- fused gate epilogue ----
    const float* xd   = g_xpt + (size_t)(d * SEGL + l) * G3 * NB;
    const float* bh   = d ? bhb : bhf;
    const float* hfin = g_hf + (size_t)(d * 2 + pp) * KP * NB;
    float*      hfout = g_hf + (size_t)(d * 2 + (pp ^ 1)) * KP * NB;
    const int nvalid = (nt == 3) ? 60 : 80;

    for (int e = tid; e < 64 * 80; e += 256) {
        int ml = e & 63, hcl = e >> 6;
        if (hcl < nvalid) {
            int m = m0 + ml;
            int hc = nt * 80 + hcl;
            float hr = Gs[ml * 241 + hcl]        + __ldg(bh + hc);
            float hz = Gs[ml * 241 + 80 + hcl]   + __ldg(bh + H + hc);
            float hn = Gs[ml * 241 + 160 + hcl]  + __ldg(bh + 2 * H + hc);
            float xr = xd[(size_t)hc * NB + m];
            float xz = xd[(size_t)(H + hc) * NB + m];
            float xn = xd[(size_t)(2 * H + hc) * NB + m];
            float r  = sigmoidf(xr + hr);
            float z  = sigmoidf(xz + hz);
            float nv = tanhf(xn + r * hn);
            float hp = hfin[(size_t)hc * NB + m];
            float hnew = (1.0f - z) * nv + z * hp;
            hfout[(size_t)hc * NB + m] = hnew;
            __nv_bfloat16 hi = __float2bfloat16(hnew);
            __nv_bfloat16 lo = __float2bfloat16(hnew - __bfloat162float(hi));
            uint32_t packed = (uint32_t)*(uint16_t*)&hi | ((uint32_t)*(uint16_t*)&lo << 16);
            Gs[ml * 241 + hcl] = hnew;
            Gs[ml * 241 + 80 + hcl] = __uint_as_float(packed);
        }
    }
    __syncthreads();

    // coalesced out write
    {
        const int nq = (nt == 3) ? 15 : 20;
        for (int e = tid; e < 64 * nq; e += 256) {
            int ml = e / nq, q = e - ml * nq;
            int m = m0 + ml;
            float4 v = make_float4(Gs[ml * 241 + q * 4],     Gs[ml * 241 + q * 4 + 1],
                                   Gs[ml * 241 + q * 4 + 2], Gs[ml * 241 + q * 4 + 3]);
            *(float4*)(out + ((size_t)m * SEGL + l) * (2 * H) + (size_t)d * H + nt * 80 + q * 4) = v;
        }
    }
    // coalesced packed bf16 h write
    {
        __nv_bfloat16* ho_hi = HB(d, pp ^ 1, 0);
        __nv_bfloat16* ho_lo = HB(d, pp ^ 1, 1);
        const int nj = (nt == 3) ? 30 : 40;
        for (int e = tid; e < 64 * nj; e += 256) {
            int ml = e / nj, j = e - ml * nj;
            int m = m0 + ml;
            uint32_t p0 = __float_as_uint(Gs[ml * 241 + 80 + 2 * j]);
            uint32_t p1 = __float_as_uint(Gs[ml * 241 + 80 + 2 * j + 1]);
            uint32_t hiw = (p0 & 0xFFFFu) | (p1 << 16);
            uint32_t low = (p0 >> 16) | (p1 & 0xFFFF0000u);
            size_t off = ((size_t)m * KP + nt * 80 + 2 * j);
            *(uint32_t*)((char*)ho_hi + off * 2) = hiw;
            *(uint32_t*)((char*)ho_lo + off * 2) = low;
        }
    }
}

// ---------------- launch ----------------
extern "C" void kernel_launch(void* const* d_in, const int* in_sizes, int n_in,
                              void* d_out, int out_size) {
    const float* x      = (const float*)d_in[0];
    const float* bias   = (const float*)d_in[4];
    const float* w_ih_f = (const float*)d_in[5];
    const float* w_hh_f = (const float*)d_in[6];
    const float* b_ih_f = (const float*)d_in[7];
    const float* b_hh_f = (const float*)d_in[8];
    const float* w_ih_b = (const float*)d_in[9];
    const float* w_hh_b = (const float*)d_in[10];
    const float* b_ih_b = (const float*)d_in[11];
    const float* b_hh_b = (const float*)d_in[12];
    float* out = (float*)d_out;

    cudaFuncSetAttribute(gru_step_mma, cudaFuncAttributeMaxDynamicSharedMemorySize, SMEM_BYTES);
    cudaFuncSetAttribute(xproj_mma,    cudaFuncAttributeMaxDynamicSharedMemorySize, SMEM_BYTES);

    setup_h0<<<NB, 128>>>(x);
    prep_whh<<<dim3(10, 4, 2), 256>>>(w_hh_f, w_hh_b);
    prep_wih<<<dim3(10, 8), 256>>>(w_ih_f, w_ih_b);

    xproj_mma<<<dim3(8, 32, SEGL), 256, SMEM_BYTES>>>(x, bias, b_ih_f, b_ih_b);

    dim3 g3(4, 32, 2);
    for (int s = 0; s < SEGL; s++) {
        gru_step_mma<<<g3, 256, SMEM_BYTES>>>(s, b_hh_f, b_hh_b, out);
    }
}